// round 1
// baseline (speedup 1.0000x reference)
#include <cuda_runtime.h>
#include <cstdint>

// Problem constants
#define B_TOT 32768
#define F_TOT 256
#define H1 16
#define H2 8

// Tiling
#define BB 128   // batch elements per block
#define FT 8     // features per block (one warp per feature)
// block = FT warps = 256 threads; each lane handles 4 batch elements.

__device__ __forceinline__ float elu_f(float v) {
    float e = __expf(v) - 1.0f;
    return v > 0.0f ? v : e;
}

__global__ __launch_bounds__(256) void mlp_z_kernel(
    const float* __restrict__ x,
    const float* __restrict__ W1, const float* __restrict__ b1,
    const float* __restrict__ W2, const float* __restrict__ b2,
    const float* __restrict__ W3, const float* __restrict__ b3,
    float* __restrict__ Z)
{
    __shared__ float s_x[FT][BB];   // f-major: conflict-free lane reads
    __shared__ float s_z[FT][BB];
    __shared__ float sW1[FT * H1];
    __shared__ float sb1[FT * H1];
    __shared__ float sW2[FT * H1 * H2];
    __shared__ float sb2[FT * H2];
    __shared__ float sW3[FT * H2];
    __shared__ float sb3[FT];

    const int t  = threadIdx.x;
    const int b0 = blockIdx.x * BB;
    const int f0 = blockIdx.y * FT;

    // ---- load per-feature params (contiguous chunks in gmem) ----
    {
        // FT*H1 = 128
        if (t < FT * H1) { sW1[t] = W1[f0 * H1 + t]; sb1[t] = b1[f0 * H1 + t]; }
        // FT*H1*H2 = 1024 -> 4 per thread
        #pragma unroll
        for (int i = t; i < FT * H1 * H2; i += 256) sW2[i] = W2[f0 * H1 * H2 + i];
        if (t < FT * H2) { sb2[t] = b2[f0 * H2 + t]; sW3[t] = W3[f0 * H2 + t]; }
        if (t < FT)      { sb3[t] = b3[f0 + t]; }
    }

    // ---- load x tile [BB x FT] coalesced, store f-major ----
    {
        const int bl = t >> 1;            // 0..127
        const int fq = (t & 1) * 4;       // 0 or 4
        const float4 v = *reinterpret_cast<const float4*>(
            x + (size_t)(b0 + bl) * F_TOT + f0 + fq);
        s_x[fq + 0][bl] = v.x;
        s_x[fq + 1][bl] = v.y;
        s_x[fq + 2][bl] = v.z;
        s_x[fq + 3][bl] = v.w;
    }
    __syncthreads();

    const int w = t >> 5;   // warp = feature index within tile
    const int l = t & 31;   // lane = batch index within 32

    float xv[4];
    #pragma unroll
    for (int u = 0; u < 4; u++) xv[u] = s_x[w][l + 32 * u];

    // h1 = elu(x * W1 + b1)
    float h1r[4][H1];
    #pragma unroll
    for (int h = 0; h < H1; h++) {
        const float wg = sW1[w * H1 + h];
        const float bb = sb1[w * H1 + h];
        #pragma unroll
        for (int u = 0; u < 4; u++)
            h1r[u][h] = elu_f(fmaf(xv[u], wg, bb));
    }

    // acc = h1 @ W2 + b2
    float acc[4][H2];
    #pragma unroll
    for (int k = 0; k < H2; k++) {
        const float bv = sb2[w * H2 + k];
        #pragma unroll
        for (int u = 0; u < 4; u++) acc[u][k] = bv;
    }
    #pragma unroll
    for (int h = 0; h < H1; h++) {
        #pragma unroll
        for (int k = 0; k < H2; k++) {
            const float w2 = sW2[w * H1 * H2 + h * H2 + k];
            #pragma unroll
            for (int u = 0; u < 4; u++)
                acc[u][k] = fmaf(h1r[u][h], w2, acc[u][k]);
        }
    }

    // Z = elu(acc) . W3 + b3
    #pragma unroll
    for (int u = 0; u < 4; u++) {
        float z = sb3[w];
        #pragma unroll
        for (int k = 0; k < H2; k++)
            z = fmaf(elu_f(acc[u][k]), sW3[w * H2 + k], z);
        s_z[w][l + 32 * u] = z;
    }
    __syncthreads();

    // ---- write Z tile coalesced (float4) ----
    {
        const int bl = t >> 1;
        const int fq = (t & 1) * 4;
        float4 v;
        v.x = s_z[fq + 0][bl];
        v.y = s_z[fq + 1][bl];
        v.z = s_z[fq + 2][bl];
        v.w = s_z[fq + 3][bl];
        *reinterpret_cast<float4*>(Z + (size_t)(b0 + bl) * F_TOT + f0 + fq) = v;
    }
}

// y[b] = sum_f Z[b,f] * softplus(theta[f]) + bias ; one warp per batch row
__global__ __launch_bounds__(256) void reduce_y_kernel(
    const float* __restrict__ Z,
    const float* __restrict__ theta,
    const float* __restrict__ bias,
    float* __restrict__ y)
{
    __shared__ float s_w[F_TOT];
    const int t = threadIdx.x;
    s_w[t] = log1pf(__expf(theta[t]));
    __syncthreads();

    const int warp = t >> 5, lane = t & 31;
    const int b = blockIdx.x * 8 + warp;
    const float* zr = Z + (size_t)b * F_TOT;
    float acc = 0.0f;
    #pragma unroll
    for (int i = 0; i < F_TOT / 32; i++)
        acc = fmaf(zr[lane + 32 * i], s_w[lane + 32 * i], acc);
    #pragma unroll
    for (int o = 16; o > 0; o >>= 1)
        acc += __shfl_xor_sync(0xFFFFFFFFu, acc, o);
    if (lane == 0) y[b] = acc + bias[0];
}

__global__ void weights_kernel(const float* __restrict__ theta, float* __restrict__ wout)
{
    const int t = threadIdx.x;
    wout[t] = log1pf(__expf(theta[t]));
}

extern "C" void kernel_launch(void* const* d_in, const int* in_sizes, int n_in,
                              void* d_out, int out_size)
{
    const float* x     = (const float*)d_in[0];
    const float* W1    = (const float*)d_in[1];
    const float* b1    = (const float*)d_in[2];
    const float* W2    = (const float*)d_in[3];
    const float* b2    = (const float*)d_in[4];
    const float* W3    = (const float*)d_in[5];
    const float* b3    = (const float*)d_in[6];
    const float* theta = (const float*)d_in[7];
    const float* bias  = (const float*)d_in[8];

    float* out = (float*)d_out;
    float* y    = out;                 // [B]
    float* wout = out + B_TOT;         // [F]
    float* Z    = out + B_TOT + F_TOT; // [B, F]

    dim3 grid(B_TOT / BB, F_TOT / FT);   // (256, 32)
    mlp_z_kernel<<<grid, 256>>>(x, W1, b1, W2, b2, W3, b3, Z);

    weights_kernel<<<1, F_TOT>>>(theta, wout);

    reduce_y_kernel<<<B_TOT / 8, 256>>>(Z, theta, bias, y);
}

// round 2
// speedup vs baseline: 1.1611x; 1.1611x over previous
#include <cuda_runtime.h>
#include <cstdint>

#define B_TOT 32768
#define F_TOT 256
#define H1 16
#define H2 8

#define BB 128   // batch elements per block
#define FT 8     // features per block (one warp per feature)

typedef unsigned long long u64;

__device__ __forceinline__ u64 f2pack(float lo, float hi) {
    u64 r; asm("mov.b64 %0, {%1, %2};" : "=l"(r) : "f"(lo), "f"(hi)); return r;
}
__device__ __forceinline__ void f2unpack(u64 p, float& lo, float& hi) {
    asm("mov.b64 {%0, %1}, %2;" : "=f"(lo), "=f"(hi) : "l"(p));
}
__device__ __forceinline__ u64 fma2(u64 a, u64 b, u64 c) {
    u64 r; asm("fma.rn.f32x2 %0, %1, %2, %3;" : "=l"(r) : "l"(a), "l"(b), "l"(c)); return r;
}
__device__ __forceinline__ u64 mul2(u64 a, u64 b) {
    u64 r; asm("mul.rn.f32x2 %0, %1, %2;" : "=l"(r) : "l"(a), "l"(b)); return r;
}
__device__ __forceinline__ u64 add2(u64 a, u64 b) {
    u64 r; asm("add.rn.f32x2 %0, %1, %2;" : "=l"(r) : "l"(a), "l"(b)); return r;
}
__device__ __forceinline__ float ex2f(float x) {
    float r; asm("ex2.approx.ftz.f32 %0, %1;" : "=f"(r) : "f"(x)); return r;
}

// Packed ELU on a batch-pair: elu(v) = v > 0 ? v : exp(v) - 1
__device__ __forceinline__ u64 elu2(u64 v2, u64 L2E2, u64 NEG1) {
    u64 t2 = mul2(v2, L2E2);          // v * log2(e)   (packed)
    float t0, t1; f2unpack(t2, t0, t1);
    float e0 = ex2f(t0);              // MUFU.EX2 (scalar, unavoidable)
    float e1 = ex2f(t1);
    u64 e2 = add2(f2pack(e0, e1), NEG1);  // exp(v) - 1  (packed)
    float v0, v1; f2unpack(v2, v0, v1);
    float ee0, ee1; f2unpack(e2, ee0, ee1);
    float r0 = v0 > 0.0f ? v0 : ee0;  // FSETP + FSEL
    float r1 = v1 > 0.0f ? v1 : ee1;
    return f2pack(r0, r1);
}

__global__ __launch_bounds__(256) void mlp_z_kernel(
    const float* __restrict__ x,
    const float* __restrict__ W1, const float* __restrict__ b1,
    const float* __restrict__ W2, const float* __restrict__ b2,
    const float* __restrict__ W3, const float* __restrict__ b3,
    float* __restrict__ Z)
{
    __shared__ float s_x[FT][BB];
    __shared__ float s_z[FT][BB];
    // Duplicated {w, w} float2 weights: packed operand via one broadcast LDS.64
    __shared__ u64 sW1d[FT * H1];
    __shared__ u64 sb1d[FT * H1];
    __shared__ u64 sW2d[FT * H1 * H2];
    __shared__ u64 sb2d[FT * H2];
    __shared__ u64 sW3d[FT * H2];
    __shared__ float sb3[FT];

    const int t  = threadIdx.x;
    const int b0 = blockIdx.x * BB;
    const int f0 = blockIdx.y * FT;

    // ---- load per-feature params, duplicating into f32x2 pairs ----
    if (t < FT * H1) {
        float w = W1[f0 * H1 + t];  sW1d[t] = f2pack(w, w);
        float b = b1[f0 * H1 + t];  sb1d[t] = f2pack(b, b);
    }
    #pragma unroll
    for (int i = t; i < FT * H1 * H2; i += 256) {
        float w = W2[f0 * H1 * H2 + i];  sW2d[i] = f2pack(w, w);
    }
    if (t < FT * H2) {
        float b = b2[f0 * H2 + t];  sb2d[t] = f2pack(b, b);
        float w = W3[f0 * H2 + t];  sW3d[t] = f2pack(w, w);
    }
    if (t < FT) sb3[t] = b3[f0 + t];

    // ---- load x tile [BB x FT] coalesced, store f-major ----
    {
        const int bl = t >> 1;
        const int fq = (t & 1) * 4;
        const float4 v = *reinterpret_cast<const float4*>(
            x + (size_t)(b0 + bl) * F_TOT + f0 + fq);
        s_x[fq + 0][bl] = v.x;
        s_x[fq + 1][bl] = v.y;
        s_x[fq + 2][bl] = v.z;
        s_x[fq + 3][bl] = v.w;
    }
    __syncthreads();

    const int w = t >> 5;
    const int l = t & 31;

    const u64 L2E2 = f2pack(1.4426950408889634f, 1.4426950408889634f);
    const u64 NEG1 = f2pack(-1.0f, -1.0f);

    u64 xp[2];
    xp[0] = f2pack(s_x[w][l],      s_x[w][l + 32]);
    xp[1] = f2pack(s_x[w][l + 64], s_x[w][l + 96]);

    // acc = b2 (packed over batch pairs)
    u64 acc[2][H2];
    #pragma unroll
    for (int k = 0; k < H2; k++) {
        const u64 bv = sb2d[w * H2 + k];
        acc[0][k] = bv;
        acc[1][k] = bv;
    }

    // main loop: per hidden unit, compute packed h1 then immediately accumulate
    #pragma unroll
    for (int h = 0; h < H1; h++) {
        const u64 w1 = sW1d[w * H1 + h];
        const u64 bb = sb1d[w * H1 + h];
        const u64 h1p0 = elu2(fma2(xp[0], w1, bb), L2E2, NEG1);
        const u64 h1p1 = elu2(fma2(xp[1], w1, bb), L2E2, NEG1);
        #pragma unroll
        for (int k = 0; k < H2; k++) {
            const u64 w2 = sW2d[(w * H1 + h) * H2 + k];
            acc[0][k] = fma2(h1p0, w2, acc[0][k]);
            acc[1][k] = fma2(h1p1, w2, acc[1][k]);
        }
    }

    // epilogue: Z = elu(acc) . W3 + b3   (packed over batch pairs)
    {
        const float b3v = sb3[w];
        u64 z[2];
        z[0] = f2pack(b3v, b3v);
        z[1] = z[0];
        #pragma unroll
        for (int k = 0; k < H2; k++) {
            const u64 w3 = sW3d[w * H2 + k];
            z[0] = fma2(elu2(acc[0][k], L2E2, NEG1), w3, z[0]);
            z[1] = fma2(elu2(acc[1][k], L2E2, NEG1), w3, z[1]);
        }
        float z0, z1, z2, z3;
        f2unpack(z[0], z0, z1);
        f2unpack(z[1], z2, z3);
        s_z[w][l]      = z0;
        s_z[w][l + 32] = z1;
        s_z[w][l + 64] = z2;
        s_z[w][l + 96] = z3;
    }
    __syncthreads();

    // ---- write Z tile coalesced (float4) ----
    {
        const int bl = t >> 1;
        const int fq = (t & 1) * 4;
        float4 v;
        v.x = s_z[fq + 0][bl];
        v.y = s_z[fq + 1][bl];
        v.z = s_z[fq + 2][bl];
        v.w = s_z[fq + 3][bl];
        *reinterpret_cast<float4*>(Z + (size_t)(b0 + bl) * F_TOT + f0 + fq) = v;
    }
}

// y[b] = sum_f Z[b,f] * softplus(theta[f]) + bias ; one warp per batch row
__global__ __launch_bounds__(256) void reduce_y_kernel(
    const float* __restrict__ Z,
    const float* __restrict__ theta,
    const float* __restrict__ bias,
    float* __restrict__ y)
{
    __shared__ float s_w[F_TOT];
    const int t = threadIdx.x;
    s_w[t] = log1pf(__expf(theta[t]));
    __syncthreads();

    const int warp = t >> 5, lane = t & 31;
    const int b = blockIdx.x * 8 + warp;
    const float* zr = Z + (size_t)b * F_TOT;
    float acc = 0.0f;
    #pragma unroll
    for (int i = 0; i < F_TOT / 32; i++)
        acc = fmaf(zr[lane + 32 * i], s_w[lane + 32 * i], acc);
    #pragma unroll
    for (int o = 16; o > 0; o >>= 1)
        acc += __shfl_xor_sync(0xFFFFFFFFu, acc, o);
    if (lane == 0) y[b] = acc + bias[0];
}

__global__ void weights_kernel(const float* __restrict__ theta, float* __restrict__ wout)
{
    const int t = threadIdx.x;
    wout[t] = log1pf(__expf(theta[t]));
}

extern "C" void kernel_launch(void* const* d_in, const int* in_sizes, int n_in,
                              void* d_out, int out_size)
{
    const float* x     = (const float*)d_in[0];
    const float* W1    = (const float*)d_in[1];
    const float* b1    = (const float*)d_in[2];
    const float* W2    = (const float*)d_in[3];
    const float* b2    = (const float*)d_in[4];
    const float* W3    = (const float*)d_in[5];
    const float* b3    = (const float*)d_in[6];
    const float* theta = (const float*)d_in[7];
    const float* bias  = (const float*)d_in[8];

    float* out = (float*)d_out;
    float* y    = out;                 // [B]
    float* wout = out + B_TOT;         // [F]
    float* Z    = out + B_TOT + F_TOT; // [B, F]

    dim3 grid(B_TOT / BB, F_TOT / FT);   // (256, 32)
    mlp_z_kernel<<<grid, 256>>>(x, W1, b1, W2, b2, W3, b3, Z);

    weights_kernel<<<1, F_TOT>>>(theta, wout);

    reduce_y_kernel<<<B_TOT / 8, 256>>>(Z, theta, bias, y);
}

// round 3
// speedup vs baseline: 1.2936x; 1.1141x over previous
#include <cuda_runtime.h>
#include <cstdint>

#define B_TOT 32768
#define F_TOT 256
#define H1 16
#define H2 8

#define BB 256   // batch elements per block (per warp: 32 lanes x 4 pairs x 2)
#define FT 8     // features per block (one warp per feature)
#define NP 4     // f32x2 pairs per thread (8 batch elements)

typedef unsigned long long u64;

__device__ __forceinline__ u64 f2pack(float lo, float hi) {
    u64 r; asm("mov.b64 %0, {%1, %2};" : "=l"(r) : "f"(lo), "f"(hi)); return r;
}
__device__ __forceinline__ void f2unpack(u64 p, float& lo, float& hi) {
    asm("mov.b64 {%0, %1}, %2;" : "=f"(lo), "=f"(hi) : "l"(p));
}
__device__ __forceinline__ u64 fma2(u64 a, u64 b, u64 c) {
    u64 r; asm("fma.rn.f32x2 %0, %1, %2, %3;" : "=l"(r) : "l"(a), "l"(b), "l"(c)); return r;
}
__device__ __forceinline__ float ex2f(float x) {
    float r; asm("ex2.approx.ftz.f32 %0, %1;" : "=f"(r) : "f"(x)); return r;
}

// Packed ELU, minimal instruction count (~14 issues/pair):
// unpack(2) + FMUL-imm(2) + MUFU(2) + FADD(2) + FSETP/FSEL(4) + pack(2)
__device__ __forceinline__ u64 elu2(u64 v2) {
    float v0, v1; f2unpack(v2, v0, v1);
    float e0 = ex2f(v0 * 1.4426950408889634f);
    float e1 = ex2f(v1 * 1.4426950408889634f);
    float r0 = v0 > 0.0f ? v0 : e0 - 1.0f;
    float r1 = v1 > 0.0f ? v1 : e1 - 1.0f;
    return f2pack(r0, r1);
}

__global__ __launch_bounds__(256) void mlp_z_kernel(
    const float* __restrict__ x,
    const float* __restrict__ W1, const float* __restrict__ b1,
    const float* __restrict__ W2, const float* __restrict__ b2,
    const float* __restrict__ W3, const float* __restrict__ b3,
    float* __restrict__ Z)
{
    __shared__ float s_x[FT][BB];     // 8 KB
    __shared__ float s_z[FT][BB];     // 8 KB
    // Duplicated {w, w} pairs: packed operand in one broadcast LDS.64
    __shared__ u64 sW1d[FT * H1];
    __shared__ u64 sb1d[FT * H1];
    __shared__ u64 sW2d[FT * H1 * H2];
    __shared__ u64 sb2d[FT * H2];
    __shared__ u64 sW3d[FT * H2];
    __shared__ float sb3[FT];

    const int t  = threadIdx.x;
    const int b0 = blockIdx.x * BB;
    const int f0 = blockIdx.y * FT;

    // ---- params -> smem (duplicated into f32x2) ----
    if (t < FT * H1) {
        float w = W1[f0 * H1 + t];  sW1d[t] = f2pack(w, w);
        float b = b1[f0 * H1 + t];  sb1d[t] = f2pack(b, b);
    }
    #pragma unroll
    for (int i = t; i < FT * H1 * H2; i += 256) {
        float w = W2[f0 * H1 * H2 + i];  sW2d[i] = f2pack(w, w);
    }
    if (t < FT * H2) {
        float b = b2[f0 * H2 + t];  sb2d[t] = f2pack(b, b);
        float w = W3[f0 * H2 + t];  sW3d[t] = f2pack(w, w);
    }
    if (t < FT) sb3[t] = b3[f0 + t];

    // ---- x tile [BB x FT] coalesced float4 -> f-major smem ----
    #pragma unroll
    for (int i = t; i < BB * 2; i += 256) {
        const int bl = i >> 1;
        const int fq = (i & 1) * 4;
        const float4 v = *reinterpret_cast<const float4*>(
            x + (size_t)(b0 + bl) * F_TOT + f0 + fq);
        s_x[fq + 0][bl] = v.x;
        s_x[fq + 1][bl] = v.y;
        s_x[fq + 2][bl] = v.z;
        s_x[fq + 3][bl] = v.w;
    }
    __syncthreads();

    const int w = t >> 5;
    const int l = t & 31;

    // 4 pairs: pair u covers batch lanes (l + 64u, l + 64u + 32)
    u64 xp[NP];
    #pragma unroll
    for (int u = 0; u < NP; u++)
        xp[u] = f2pack(s_x[w][l + 64 * u], s_x[w][l + 64 * u + 32]);

    u64 acc[NP][H2];
    #pragma unroll
    for (int k = 0; k < H2; k++) {
        const u64 bv = sb2d[w * H2 + k];
        #pragma unroll
        for (int u = 0; u < NP; u++) acc[u][k] = bv;
    }

    #pragma unroll
    for (int h = 0; h < H1; h++) {
        const u64 w1 = sW1d[w * H1 + h];
        const u64 bb = sb1d[w * H1 + h];
        u64 h1p[NP];
        #pragma unroll
        for (int u = 0; u < NP; u++)
            h1p[u] = elu2(fma2(xp[u], w1, bb));
        #pragma unroll
        for (int k = 0; k < H2; k++) {
            const u64 w2 = sW2d[(w * H1 + h) * H2 + k];
            #pragma unroll
            for (int u = 0; u < NP; u++)
                acc[u][k] = fma2(h1p[u], w2, acc[u][k]);
        }
    }

    // epilogue: Z = elu(acc) . W3 + b3
    {
        const float b3v = sb3[w];
        #pragma unroll
        for (int u = 0; u < NP; u++) {
            u64 z = f2pack(b3v, b3v);
            #pragma unroll
            for (int k = 0; k < H2; k++)
                z = fma2(elu2(acc[u][k]), sW3d[w * H2 + k], z);
            float z0, z1; f2unpack(z, z0, z1);
            s_z[w][l + 64 * u]      = z0;
            s_z[w][l + 64 * u + 32] = z1;
        }
    }
    __syncthreads();

    // ---- Z tile -> gmem coalesced float4 ----
    #pragma unroll
    for (int i = t; i < BB * 2; i += 256) {
        const int bl = i >> 1;
        const int fq = (i & 1) * 4;
        float4 v;
        v.x = s_z[fq + 0][bl];
        v.y = s_z[fq + 1][bl];
        v.z = s_z[fq + 2][bl];
        v.w = s_z[fq + 3][bl];
        *reinterpret_cast<float4*>(Z + (size_t)(b0 + bl) * F_TOT + f0 + fq) = v;
    }
}

// y[b] = sum_f Z[b,f] * softplus(theta[f]) + bias ; one warp per batch row
__global__ __launch_bounds__(256) void reduce_y_kernel(
    const float* __restrict__ Z,
    const float* __restrict__ theta,
    const float* __restrict__ bias,
    float* __restrict__ y)
{
    __shared__ float s_w[F_TOT];
    const int t = threadIdx.x;
    s_w[t] = log1pf(__expf(theta[t]));
    __syncthreads();

    const int warp = t >> 5, lane = t & 31;
    const int b = blockIdx.x * 8 + warp;
    const float* zr = Z + (size_t)b * F_TOT;
    float acc = 0.0f;
    #pragma unroll
    for (int i = 0; i < F_TOT / 32; i++)
        acc = fmaf(zr[lane + 32 * i], s_w[lane + 32 * i], acc);
    #pragma unroll
    for (int o = 16; o > 0; o >>= 1)
        acc += __shfl_xor_sync(0xFFFFFFFFu, acc, o);
    if (lane == 0) y[b] = acc + bias[0];
}

__global__ void weights_kernel(const float* __restrict__ theta, float* __restrict__ wout)
{
    const int t = threadIdx.x;
    wout[t] = log1pf(__expf(theta[t]));
}

extern "C" void kernel_launch(void* const* d_in, const int* in_sizes, int n_in,
                              void* d_out, int out_size)
{
    const float* x     = (const float*)d_in[0];
    const float* W1    = (const float*)d_in[1];
    const float* b1    = (const float*)d_in[2];
    const float* W2    = (const float*)d_in[3];
    const float* b2    = (const float*)d_in[4];
    const float* W3    = (const float*)d_in[5];
    const float* b3    = (const float*)d_in[6];
    const float* theta = (const float*)d_in[7];
    const float* bias  = (const float*)d_in[8];

    float* out = (float*)d_out;
    float* y    = out;                 // [B]
    float* wout = out + B_TOT;         // [F]
    float* Z    = out + B_TOT + F_TOT; // [B, F]

    dim3 grid(B_TOT / BB, F_TOT / FT);   // (128, 32)
    mlp_z_kernel<<<grid, 256>>>(x, W1, b1, W2, b2, W3, b3, Z);

    weights_kernel<<<1, F_TOT>>>(theta, wout);

    reduce_y_kernel<<<B_TOT / 8, 256>>>(Z, theta, bias, y);
}